// round 1
// baseline (speedup 1.0000x reference)
#include <cuda_runtime.h>
#include <cstdint>

#define N_NODES  100000
#define N_EDGES  1600000
#define IN_CH    128
#define HID      64
#define N_GRAPHS 64
#define OUT_CH   10

// ---------------- scratch (static device allocations; no cudaMalloc) ----------------
__device__ float g_deg[N_NODES];
__device__ float g_dinv[N_NODES];
__device__ float g_xw [(size_t)N_NODES * HID];
__device__ float g_agg[(size_t)N_NODES * HID];
__device__ float g_h  [(size_t)N_NODES * HID];
__device__ float g_pool[N_GRAPHS * HID];
__device__ float g_cnt [N_GRAPHS];
__device__ int   g_is64;

// ---------------- index dtype helpers (int32 vs int64, detected at runtime) ----------
__device__ __forceinline__ long long ld_idx(const void* p, long long i, int is64) {
    if (is64) return ((const long long*)p)[i];
    return (long long)((const int*)p)[i];
}

__global__ void detect_kernel(const void* ei) {
    // If the buffer really is int64, the first 64 values are valid node ids.
    // If it is int32, the int64 reinterpretation combines pairs -> huge values.
    const long long* p = (const long long*)ei;
    int ok = 1;
    for (int i = 0; i < 64; i++) {
        long long v = p[i];
        if (v < 0 || v >= N_NODES) { ok = 0; break; }
    }
    g_is64 = ok;
}

// ---------------- degree / norm ----------------
__global__ void init_kernel() {
    int i = blockIdx.x * blockDim.x + threadIdx.x;
    if (i < N_NODES) g_deg[i] = 1.0f;            // self-loop contribution
    if (i < N_GRAPHS * HID) g_pool[i] = 0.0f;
    if (i < N_GRAPHS) g_cnt[i] = 0.0f;
}

__global__ void deg_kernel(const void* ei) {
    int e = blockIdx.x * blockDim.x + threadIdx.x;
    if (e >= N_EDGES) return;
    int is64 = g_is64;
    long long c = ld_idx(ei, (long long)N_EDGES + e, is64);
    atomicAdd(&g_deg[c], 1.0f);
}

__global__ void dinv_kernel() {
    int i = blockIdx.x * blockDim.x + threadIdx.x;
    if (i < N_NODES) g_dinv[i] = rsqrtf(g_deg[i]);
}

// ---------------- dense GEMM: Y[n,64] = X[n,K] @ W[K,64] ----------------
// 256 threads / block, 32 rows / block. Per thread: 2 rows x 4 cols register tile.
template <int K>
__global__ void gemm_kernel(const float* __restrict__ X, const float* __restrict__ W,
                            float* __restrict__ Y, int n) {
    __shared__ float Ws[K * 64];
    __shared__ float Xs[32 * K];
    int t = threadIdx.x;
    for (int i = t; i < K * 64; i += 256) Ws[i] = W[i];
    int row0 = blockIdx.x * 32;
    for (int i = t; i < 32 * K; i += 256) {
        int r = i / K, k = i % K;
        int gr = row0 + r;
        Xs[i] = (gr < n) ? X[(size_t)gr * K + k] : 0.0f;
    }
    __syncthreads();

    int c0 = (t & 15) * 4;     // 16 col-groups x 4 cols = 64 cols
    int r0 = (t >> 4) * 2;     // 16 row-slots x 2 rows = 32 rows
    float4 acc0 = make_float4(0.f, 0.f, 0.f, 0.f);
    float4 acc1 = make_float4(0.f, 0.f, 0.f, 0.f);

    #pragma unroll 4
    for (int k = 0; k < K; k += 4) {
        float4 xv0 = *(const float4*)&Xs[r0 * K + k];
        float4 xv1 = *(const float4*)&Xs[(r0 + 1) * K + k];
        #pragma unroll
        for (int kk = 0; kk < 4; kk++) {
            float4 wv = *(const float4*)&Ws[(k + kk) * 64 + c0];
            float x0 = kk == 0 ? xv0.x : kk == 1 ? xv0.y : kk == 2 ? xv0.z : xv0.w;
            float x1 = kk == 0 ? xv1.x : kk == 1 ? xv1.y : kk == 2 ? xv1.z : xv1.w;
            acc0.x += x0 * wv.x; acc0.y += x0 * wv.y; acc0.z += x0 * wv.z; acc0.w += x0 * wv.w;
            acc1.x += x1 * wv.x; acc1.y += x1 * wv.y; acc1.z += x1 * wv.z; acc1.w += x1 * wv.w;
        }
    }
    int gr0 = row0 + r0;
    if (gr0 < n)     *(float4*)&Y[(size_t)gr0 * 64 + c0]       = acc0;
    if (gr0 + 1 < n) *(float4*)&Y[(size_t)(gr0 + 1) * 64 + c0] = acc1;
}

// ---------------- agg = xw * dinv^2  (self loop term) ----------------
__global__ void agg_init_kernel() {
    int gid = blockIdx.x * blockDim.x + threadIdx.x;   // one float4 per thread
    if (gid >= N_NODES * 16) return;
    int node = gid >> 4;
    float d = g_dinv[node];
    float s = d * d;
    float4 v = *(const float4*)&g_xw[(size_t)gid * 4];
    v.x *= s; v.y *= s; v.z *= s; v.w *= s;
    *(float4*)&g_agg[(size_t)gid * 4] = v;
}

// ---------------- edge scatter: agg[col] += dinv[row]*dinv[col] * xw[row] ----------
__global__ void scatter_kernel(const void* ei) {
    long long gid = (long long)blockIdx.x * blockDim.x + threadIdx.x;
    long long e = gid >> 4;           // 16 threads per edge, 4 channels each
    if (e >= N_EDGES) return;
    int c4 = (int)(gid & 15);
    int is64 = g_is64;
    long long r = ld_idx(ei, e, is64);
    long long c = ld_idx(ei, (long long)N_EDGES + e, is64);
    float nrm = g_dinv[r] * g_dinv[c];
    float4 v = *(const float4*)&g_xw[(size_t)r * 64 + c4 * 4];
    float* dst = &g_agg[(size_t)c * 64 + c4 * 4];
    asm volatile("red.global.add.v4.f32 [%0], {%1,%2,%3,%4};"
                 :: "l"(dst), "f"(v.x * nrm), "f"(v.y * nrm), "f"(v.z * nrm), "f"(v.w * nrm)
                 : "memory");
}

// ---------------- h = relu(agg + b) ----------------
__global__ void relu_bias_kernel(const float* __restrict__ b) {
    int gid = blockIdx.x * blockDim.x + threadIdx.x;
    if (gid >= N_NODES * 16) return;
    float4 bv = ((const float4*)b)[gid & 15];
    float4 v = *(const float4*)&g_agg[(size_t)gid * 4];
    v.x = fmaxf(v.x + bv.x, 0.f);
    v.y = fmaxf(v.y + bv.y, 0.f);
    v.z = fmaxf(v.z + bv.z, 0.f);
    v.w = fmaxf(v.w + bv.w, 0.f);
    *(float4*)&g_h[(size_t)gid * 4] = v;
}

// ---------------- global mean pool (batch is sorted -> local accumulate) ----------
#define NPB 512
__global__ void pool_kernel(const void* batch) {
    int c = threadIdx.x;                       // 64 channels
    int n0 = blockIdx.x * NPB;
    if (n0 >= N_NODES) return;
    int nend = min(n0 + NPB, N_NODES);
    int is64 = g_is64;
    long long curg = ld_idx(batch, n0, is64);
    float acc = 0.f, count = 0.f;
    for (int nn = n0; nn < nend; nn++) {
        long long g = ld_idx(batch, nn, is64);
        if (g != curg) {
            atomicAdd(&g_pool[curg * HID + c], acc);
            if (c == 0) atomicAdd(&g_cnt[curg], count);
            acc = 0.f; count = 0.f; curg = g;
        }
        acc += g_h[(size_t)nn * HID + c];
        count += 1.f;
    }
    atomicAdd(&g_pool[curg * HID + c], acc);
    if (c == 0) atomicAdd(&g_cnt[curg], count);
}

// ---------------- final: out[g,o] = (pool[g]/cnt[g]) @ Wl + bl ----------------
__global__ void final_kernel(const float* __restrict__ Wl, const float* __restrict__ bl,
                             float* __restrict__ out) {
    int g = blockIdx.x;
    int o = threadIdx.x;
    if (o >= OUT_CH) return;
    float inv = 1.0f / fmaxf(g_cnt[g], 1.0f);
    float s = 0.0f;
    #pragma unroll
    for (int c = 0; c < HID; c++)
        s += g_pool[g * HID + c] * Wl[c * OUT_CH + o];
    out[g * OUT_CH + o] = s * inv + bl[o];
}

// ---------------- launch ----------------
extern "C" void kernel_launch(void* const* d_in, const int* in_sizes, int n_in,
                              void* d_out, int out_size) {
    const float* x  = (const float*)d_in[0];
    const float* W1 = (const float*)d_in[1];
    const float* b1 = (const float*)d_in[2];
    const float* W2 = (const float*)d_in[3];
    const float* b2 = (const float*)d_in[4];
    const float* Wl = (const float*)d_in[5];
    const float* bl = (const float*)d_in[6];
    const void*  ei = d_in[7];
    const void*  batch = d_in[8];
    float* out = (float*)d_out;

    float *xw = nullptr, *h = nullptr;
    cudaGetSymbolAddress((void**)&xw, g_xw);
    cudaGetSymbolAddress((void**)&h,  g_h);

    const int T = 256;
    int nb_nodes = (N_NODES + T - 1) / T;
    int nb_edges = (N_EDGES + T - 1) / T;
    int nb_elem  = (N_NODES * 16 + T - 1) / T;
    long long sc_threads = (long long)N_EDGES * 16;
    int nb_scatter = (int)((sc_threads + T - 1) / T);
    int nb_gemm = (N_NODES + 31) / 32;

    detect_kernel<<<1, 1>>>(ei);
    init_kernel<<<nb_nodes, T>>>();
    deg_kernel<<<nb_edges, T>>>(ei);
    dinv_kernel<<<nb_nodes, T>>>();

    // layer 1
    gemm_kernel<IN_CH><<<nb_gemm, T>>>(x, W1, xw, N_NODES);
    agg_init_kernel<<<nb_elem, T>>>();
    scatter_kernel<<<nb_scatter, T>>>(ei);
    relu_bias_kernel<<<nb_elem, T>>>(b1);

    // layer 2
    gemm_kernel<HID><<<nb_gemm, T>>>(h, W2, xw, N_NODES);
    agg_init_kernel<<<nb_elem, T>>>();
    scatter_kernel<<<nb_scatter, T>>>(ei);
    relu_bias_kernel<<<nb_elem, T>>>(b2);

    // pool + classifier
    pool_kernel<<<(N_NODES + NPB - 1) / NPB, HID>>>(batch);
    final_kernel<<<N_GRAPHS, 32>>>(Wl, bl, out);
}

// round 2
// speedup vs baseline: 1.2492x; 1.2492x over previous
#include <cuda_runtime.h>
#include <cstdint>

#define N_NODES  100000
#define N_EDGES  1600000
#define IN_CH    128
#define HID      64
#define N_GRAPHS 64
#define OUT_CH   10

#define SCAN_BLOCKS ((N_NODES + 255) / 256)   // 391

// ---------------- scratch (static device arrays; no cudaMalloc) ----------------
__device__ float g_dinv[N_NODES];
__device__ float g_xw [(size_t)N_NODES * HID];
__device__ float g_h  [(size_t)N_NODES * HID];
__device__ float g_h2 [(size_t)N_NODES * HID];
__device__ float g_pool[N_GRAPHS * HID];
__device__ float g_gcnt[N_GRAPHS];
__device__ int   g_is64;

__device__ int g_cnt_i[N_NODES];
__device__ int g_rowstart[N_NODES + 1];
__device__ int g_cursor[N_NODES];
__device__ int g_blockoff[512];

struct __align__(8) Edge { int r; float w; };
__device__ Edge g_edges[N_EDGES];

// ---------------- index dtype helpers ----------------
__device__ __forceinline__ long long ld_idx(const void* p, long long i, int is64) {
    if (is64) return ((const long long*)p)[i];
    return (long long)((const int*)p)[i];
}

__global__ void detect_kernel(const void* ei) {
    const long long* p = (const long long*)ei;
    int ok = 1;
    for (int i = 0; i < 64; i++) {
        long long v = p[i];
        if (v < 0 || v >= N_NODES) { ok = 0; break; }
    }
    g_is64 = ok;
}

// ---------------- zero counters ----------------
__global__ void zero_kernel() {
    int i = blockIdx.x * blockDim.x + threadIdx.x;
    if (i < N_NODES) g_cnt_i[i] = 0;
    if (i < N_GRAPHS * HID) g_pool[i] = 0.0f;
    if (i < N_GRAPHS) g_gcnt[i] = 0.0f;
    if (i == 0) g_rowstart[N_NODES] = N_EDGES;
}

// ---------------- degree count (in-degree on col) ----------------
__global__ void count_kernel(const void* ei) {
    int e = blockIdx.x * blockDim.x + threadIdx.x;
    if (e >= N_EDGES) return;
    long long c = ld_idx(ei, (long long)N_EDGES + e, g_is64);
    atomicAdd(&g_cnt_i[(int)c], 1);
}

// ---------------- dinv = rsqrt(count + 1 self-loop) ----------------
__global__ void dinv_kernel() {
    int i = blockIdx.x * blockDim.x + threadIdx.x;
    if (i < N_NODES) g_dinv[i] = rsqrtf((float)g_cnt_i[i] + 1.0f);
}

// ---------------- prefix scan: per-block sums ----------------
__global__ void scanA_kernel() {
    __shared__ int sh[256];
    int t = threadIdx.x;
    int i = blockIdx.x * 256 + t;
    sh[t] = (i < N_NODES) ? g_cnt_i[i] : 0;
    __syncthreads();
    for (int s = 128; s > 0; s >>= 1) {
        if (t < s) sh[t] += sh[t + s];
        __syncthreads();
    }
    if (t == 0) g_blockoff[blockIdx.x] = sh[0];
}

// ---------------- prefix scan: exclusive scan of block sums (1 block) ----------------
__global__ void scanB_kernel() {
    __shared__ int sh[512];
    int t = threadIdx.x;
    int v = (t < SCAN_BLOCKS) ? g_blockoff[t] : 0;
    sh[t] = v;
    __syncthreads();
    // Hillis-Steele inclusive scan
    for (int s = 1; s < 512; s <<= 1) {
        int add = (t >= s) ? sh[t - s] : 0;
        __syncthreads();
        sh[t] += add;
        __syncthreads();
    }
    if (t < SCAN_BLOCKS) g_blockoff[t] = sh[t] - v;   // exclusive
}

// ---------------- prefix scan: per-element rowstart + cursor ----------------
__global__ void scanC_kernel() {
    __shared__ int sh[256];
    int t = threadIdx.x;
    int i = blockIdx.x * 256 + t;
    int v = (i < N_NODES) ? g_cnt_i[i] : 0;
    sh[t] = v;
    __syncthreads();
    for (int s = 1; s < 256; s <<= 1) {
        int add = (t >= s) ? sh[t - s] : 0;
        __syncthreads();
        sh[t] += add;
        __syncthreads();
    }
    if (i < N_NODES) {
        int start = g_blockoff[blockIdx.x] + sh[t] - v;  // exclusive
        g_rowstart[i] = start;
        g_cursor[i] = start;
    }
}

// ---------------- fill CSR with precomputed norm weight ----------------
__global__ void fill_kernel(const void* ei) {
    int e = blockIdx.x * blockDim.x + threadIdx.x;
    if (e >= N_EDGES) return;
    int is64 = g_is64;
    int r = (int)ld_idx(ei, e, is64);
    int c = (int)ld_idx(ei, (long long)N_EDGES + e, is64);
    float w = g_dinv[r] * g_dinv[c];
    int pos = atomicAdd(&g_cursor[c], 1);
    Edge ed; ed.r = r; ed.w = w;
    g_edges[pos] = ed;
}

// ---------------- dense GEMM: Y[n,64] = X[n,K] @ W[K,64] ----------------
template <int K>
__global__ void gemm_kernel(const float* __restrict__ X, const float* __restrict__ W,
                            float* __restrict__ Y, int n) {
    __shared__ float Ws[K * 64];
    __shared__ float Xs[32 * K];
    int t = threadIdx.x;
    for (int i = t; i < K * 64; i += 256) Ws[i] = W[i];
    int row0 = blockIdx.x * 32;
    for (int i = t; i < 32 * K; i += 256) {
        int r = i / K, k = i % K;
        int gr = row0 + r;
        Xs[i] = (gr < n) ? X[(size_t)gr * K + k] : 0.0f;
    }
    __syncthreads();

    int c0 = (t & 15) * 4;
    int r0 = (t >> 4) * 2;
    float4 acc0 = make_float4(0.f, 0.f, 0.f, 0.f);
    float4 acc1 = make_float4(0.f, 0.f, 0.f, 0.f);

    #pragma unroll 4
    for (int k = 0; k < K; k += 4) {
        float4 xv0 = *(const float4*)&Xs[r0 * K + k];
        float4 xv1 = *(const float4*)&Xs[(r0 + 1) * K + k];
        #pragma unroll
        for (int kk = 0; kk < 4; kk++) {
            float4 wv = *(const float4*)&Ws[(k + kk) * 64 + c0];
            float x0 = kk == 0 ? xv0.x : kk == 1 ? xv0.y : kk == 2 ? xv0.z : xv0.w;
            float x1 = kk == 0 ? xv1.x : kk == 1 ? xv1.y : kk == 2 ? xv1.z : xv1.w;
            acc0.x += x0 * wv.x; acc0.y += x0 * wv.y; acc0.z += x0 * wv.z; acc0.w += x0 * wv.w;
            acc1.x += x1 * wv.x; acc1.y += x1 * wv.y; acc1.z += x1 * wv.z; acc1.w += x1 * wv.w;
        }
    }
    int gr0 = row0 + r0;
    if (gr0 < n)     *(float4*)&Y[(size_t)gr0 * 64 + c0]       = acc0;
    if (gr0 + 1 < n) *(float4*)&Y[(size_t)(gr0 + 1) * 64 + c0] = acc1;
}

// ---------------- fused gather-aggregate + self-loop + bias + relu ----------------
// 16 threads per node (4 channels x float4 each); 16 nodes per 256-thread block.
__global__ void gather_kernel(const float* __restrict__ xw, const float* __restrict__ bias,
                              float* __restrict__ out) {
    int node = blockIdx.x * 16 + (threadIdx.x >> 4);
    if (node >= N_NODES) return;
    int c4 = threadIdx.x & 15;

    int s = g_rowstart[node];
    int e = g_rowstart[node + 1];
    float dc = g_dinv[node];

    // self-loop term: dinv[c]^2 * xw[c]
    float4 acc = *(const float4*)&xw[(size_t)node * 64 + c4 * 4];
    float sl = dc * dc;
    acc.x *= sl; acc.y *= sl; acc.z *= sl; acc.w *= sl;

    int i = s;
    // unroll-by-2 for load-level parallelism
    for (; i + 1 < e; i += 2) {
        Edge e0 = g_edges[i];
        Edge e1 = g_edges[i + 1];
        float4 v0 = *(const float4*)&xw[(size_t)e0.r * 64 + c4 * 4];
        float4 v1 = *(const float4*)&xw[(size_t)e1.r * 64 + c4 * 4];
        acc.x += e0.w * v0.x; acc.y += e0.w * v0.y; acc.z += e0.w * v0.z; acc.w += e0.w * v0.w;
        acc.x += e1.w * v1.x; acc.y += e1.w * v1.y; acc.z += e1.w * v1.z; acc.w += e1.w * v1.w;
    }
    if (i < e) {
        Edge e0 = g_edges[i];
        float4 v0 = *(const float4*)&xw[(size_t)e0.r * 64 + c4 * 4];
        acc.x += e0.w * v0.x; acc.y += e0.w * v0.y; acc.z += e0.w * v0.z; acc.w += e0.w * v0.w;
    }

    float4 bv = ((const float4*)bias)[c4];
    acc.x = fmaxf(acc.x + bv.x, 0.f);
    acc.y = fmaxf(acc.y + bv.y, 0.f);
    acc.z = fmaxf(acc.z + bv.z, 0.f);
    acc.w = fmaxf(acc.w + bv.w, 0.f);
    *(float4*)&out[(size_t)node * 64 + c4 * 4] = acc;
}

// ---------------- global mean pool (batch sorted -> local accumulate) ----------------
#define NPB 512
__global__ void pool_kernel(const void* batch, const float* __restrict__ h) {
    int c = threadIdx.x;
    int n0 = blockIdx.x * NPB;
    if (n0 >= N_NODES) return;
    int nend = min(n0 + NPB, N_NODES);
    int is64 = g_is64;
    long long curg = ld_idx(batch, n0, is64);
    float acc = 0.f, count = 0.f;
    for (int nn = n0; nn < nend; nn++) {
        long long g = ld_idx(batch, nn, is64);
        if (g != curg) {
            atomicAdd(&g_pool[curg * HID + c], acc);
            if (c == 0) atomicAdd(&g_gcnt[curg], count);
            acc = 0.f; count = 0.f; curg = g;
        }
        acc += h[(size_t)nn * HID + c];
        count += 1.f;
    }
    atomicAdd(&g_pool[curg * HID + c], acc);
    if (c == 0) atomicAdd(&g_gcnt[curg], count);
}

// ---------------- final classifier ----------------
__global__ void final_kernel(const float* __restrict__ Wl, const float* __restrict__ bl,
                             float* __restrict__ out) {
    int g = blockIdx.x;
    int o = threadIdx.x;
    if (o >= OUT_CH) return;
    float inv = 1.0f / fmaxf(g_gcnt[g], 1.0f);
    float s = 0.0f;
    #pragma unroll
    for (int c = 0; c < HID; c++)
        s += g_pool[g * HID + c] * Wl[c * OUT_CH + o];
    out[g * OUT_CH + o] = s * inv + bl[o];
}

// ---------------- launch ----------------
extern "C" void kernel_launch(void* const* d_in, const int* in_sizes, int n_in,
                              void* d_out, int out_size) {
    const float* x  = (const float*)d_in[0];
    const float* W1 = (const float*)d_in[1];
    const float* b1 = (const float*)d_in[2];
    const float* W2 = (const float*)d_in[3];
    const float* b2 = (const float*)d_in[4];
    const float* Wl = (const float*)d_in[5];
    const float* bl = (const float*)d_in[6];
    const void*  ei = d_in[7];
    const void*  batch = d_in[8];
    float* out = (float*)d_out;

    float *xw = nullptr, *h = nullptr, *h2 = nullptr;
    cudaGetSymbolAddress((void**)&xw, g_xw);
    cudaGetSymbolAddress((void**)&h,  g_h);
    cudaGetSymbolAddress((void**)&h2, g_h2);

    const int T = 256;
    int nb_nodes = (N_NODES + T - 1) / T;         // 391
    int nb_edges = (N_EDGES + T - 1) / T;
    int nb_gemm  = (N_NODES + 31) / 32;
    int nb_gather = (N_NODES + 15) / 16;

    detect_kernel<<<1, 1>>>(ei);
    zero_kernel<<<nb_nodes, T>>>();
    count_kernel<<<nb_edges, T>>>(ei);
    dinv_kernel<<<nb_nodes, T>>>();
    scanA_kernel<<<SCAN_BLOCKS, 256>>>();
    scanB_kernel<<<1, 512>>>();
    scanC_kernel<<<SCAN_BLOCKS, 256>>>();
    fill_kernel<<<nb_edges, T>>>(ei);

    // layer 1
    gemm_kernel<IN_CH><<<nb_gemm, T>>>(x, W1, xw, N_NODES);
    gather_kernel<<<nb_gather, T>>>(xw, b1, h);

    // layer 2
    gemm_kernel<HID><<<nb_gemm, T>>>(h, W2, xw, N_NODES);
    gather_kernel<<<nb_gather, T>>>(xw, b2, h2);

    // pool + classifier
    pool_kernel<<<(N_NODES + NPB - 1) / NPB, HID>>>(batch, h2);
    final_kernel<<<N_GRAPHS, 32>>>(Wl, bl, out);
}

// round 3
// speedup vs baseline: 1.5370x; 1.2304x over previous
#include <cuda_runtime.h>
#include <cstdint>

#define N_NODES  100000
#define N_EDGES  1600000
#define IN_CH    128
#define HID      64
#define N_GRAPHS 64
#define OUT_CH   10
#define SCAN_BLOCKS ((N_NODES + 255) / 256)   // 391

// ---------------- scratch (static device arrays; no cudaMalloc) ----------------
__device__ float g_dinv[N_NODES];
__device__ float g_xw [(size_t)N_NODES * HID];
__device__ float g_h  [(size_t)N_NODES * HID];
__device__ float g_h2 [(size_t)N_NODES * HID];
__device__ float g_pool[N_GRAPHS * HID];
__device__ float g_gcnt[N_GRAPHS];
__device__ int   g_is64;

__device__ int g_cnt_i[N_NODES];
__device__ int g_rowstart[N_NODES + 1];
__device__ int g_cursor[N_NODES];
__device__ unsigned long long g_pkt[SCAN_BLOCKS];  // decoupled-lookback packets

struct __align__(8) Edge { int r; float w; };
__device__ Edge g_edges[N_EDGES];

// ---------------- index dtype helper ----------------
__device__ __forceinline__ long long ld_idx(const void* p, long long i, int is64) {
    if (is64) return ((const long long*)p)[i];
    return (long long)((const int*)p)[i];
}

// ---------------- 0: zero scratch + detect index dtype ----------------
__global__ void zero_detect_kernel(const void* ei) {
    int i = blockIdx.x * blockDim.x + threadIdx.x;
    if (i < N_NODES) g_cnt_i[i] = 0;
    if (i < SCAN_BLOCKS) g_pkt[i] = 0ull;
    if (i < N_GRAPHS * HID) g_pool[i] = 0.0f;
    if (i < N_GRAPHS) g_gcnt[i] = 0.0f;
    if (i == 0) g_rowstart[N_NODES] = N_EDGES;
    if (blockIdx.x == 0 && threadIdx.x < 32) {
        // int64 interpretation of int32 data pairs -> out-of-range values
        const long long* p = (const long long*)ei;
        long long v = p[threadIdx.x];
        unsigned ok = __ballot_sync(0xffffffffu, v >= 0 && v < N_NODES);
        if (threadIdx.x == 0) g_is64 = (ok == 0xffffffffu) ? 1 : 0;
    }
}

// ---------------- 1: in-degree count ----------------
__global__ void count_kernel(const void* ei) {
    int e = blockIdx.x * blockDim.x + threadIdx.x;
    if (e >= N_EDGES) return;
    int c = (int)ld_idx(ei, (long long)N_EDGES + e, g_is64);
    atomicAdd(&g_cnt_i[c], 1);
}

// ---------------- 2: single-kernel exclusive scan (decoupled lookback) + dinv ----
#define FLAG_AGG (1ull << 32)
#define FLAG_INC (2ull << 32)

__global__ void scan_kernel() {
    __shared__ int sh[256];
    __shared__ int s_prefix;
    int t = threadIdx.x;
    int b = blockIdx.x;
    int i = b * 256 + t;
    int v = (i < N_NODES) ? g_cnt_i[i] : 0;

    // block-local inclusive scan (Hillis-Steele)
    sh[t] = v;
    __syncthreads();
    #pragma unroll
    for (int s = 1; s < 256; s <<= 1) {
        int a = (t >= s) ? sh[t - s] : 0;
        __syncthreads();
        sh[t] += a;
        __syncthreads();
    }
    int incl = sh[t];
    int agg = sh[255];

    if (t == 0) {
        __threadfence();
        atomicExch(&g_pkt[b], FLAG_AGG | (unsigned long long)(unsigned)agg);
    }

    // warp 0 lookback
    if (t < 32) {
        int prefix = 0;
        int idx = b - 1;
        while (idx >= 0) {
            int look = idx - t;
            unsigned long long pkt = 0ull;
            if (look >= 0) {
                do { pkt = atomicAdd(&g_pkt[look], 0ull); } while ((pkt >> 32) == 0ull);
            }
            unsigned incmask = __ballot_sync(0xffffffffu, look >= 0 && (pkt >> 32) == 2ull);
            int val = (int)(unsigned)pkt;
            if (incmask) {
                int firstinc = __ffs(incmask) - 1;   // closest predecessor with INCLUSIVE
                int contrib = (t <= firstinc) ? val : 0;
                #pragma unroll
                for (int o = 16; o; o >>= 1) contrib += __shfl_down_sync(0xffffffffu, contrib, o);
                prefix += __shfl_sync(0xffffffffu, contrib, 0);
                break;
            } else {
                int contrib = (look >= 0) ? val : 0;
                #pragma unroll
                for (int o = 16; o; o >>= 1) contrib += __shfl_down_sync(0xffffffffu, contrib, o);
                prefix += __shfl_sync(0xffffffffu, contrib, 0);
                idx -= 32;
            }
        }
        if (t == 0) {
            s_prefix = prefix;
            __threadfence();
            atomicExch(&g_pkt[b], FLAG_INC | (unsigned long long)(unsigned)(prefix + agg));
        }
    }
    __syncthreads();
    int prefix = s_prefix;

    if (i < N_NODES) {
        int start = prefix + incl - v;   // exclusive
        g_rowstart[i] = start;
        g_cursor[i] = start;
        g_dinv[i] = rsqrtf((float)v + 1.0f);   // +1 self-loop
    }
}

// ---------------- 3: fill CSR with precomputed norm weight ----------------
__global__ void fill_kernel(const void* ei) {
    int e = blockIdx.x * blockDim.x + threadIdx.x;
    if (e >= N_EDGES) return;
    int is64 = g_is64;
    int r = (int)ld_idx(ei, e, is64);
    int c = (int)ld_idx(ei, (long long)N_EDGES + e, is64);
    float w = g_dinv[r] * g_dinv[c];
    int pos = atomicAdd(&g_cursor[c], 1);
    Edge ed; ed.r = r; ed.w = w;
    g_edges[pos] = ed;
}

// ---------------- GEMM: Y[n,64] = X[n,K] @ W[K,64], 8x4 thread tile --------------
// block = 128 rows x 64 cols, 256 threads; K processed in 64-wide chunks.
template <int K>
__global__ void __launch_bounds__(256, 2) gemm_kernel(
        const float* __restrict__ X, const float* __restrict__ W,
        float* __restrict__ Y, int n) {
    __shared__ float Ws[64 * 64];    // 16 KB
    __shared__ float Xs[128 * 64];   // 32 KB
    int t = threadIdx.x;
    int row0 = blockIdx.x * 128;
    int c0 = (t & 15) * 4;
    int r0 = (t >> 4) * 8;

    float4 acc[8];
    #pragma unroll
    for (int r = 0; r < 8; r++) acc[r] = make_float4(0.f, 0.f, 0.f, 0.f);

    for (int k0 = 0; k0 < K; k0 += 64) {
        // load W chunk: rows k0..k0+63 (64x64)
        for (int i = t; i < 64 * 16; i += 256) {
            int kr = i >> 4, cq = i & 15;
            ((float4*)Ws)[i] = ((const float4*)(W + (size_t)(k0 + kr) * 64))[cq];
        }
        // load X chunk: 128 rows x 64 cols
        for (int i = t; i < 128 * 16; i += 256) {
            int r = i >> 4, kq = i & 15;
            int gr = row0 + r;
            float4 v = (gr < n) ? *(const float4*)(X + (size_t)gr * K + k0 + kq * 4)
                                : make_float4(0.f, 0.f, 0.f, 0.f);
            ((float4*)Xs)[i] = v;
        }
        __syncthreads();

        #pragma unroll 4
        for (int k = 0; k < 64; k += 4) {
            float4 xv[8];
            #pragma unroll
            for (int r = 0; r < 8; r++) xv[r] = *(const float4*)&Xs[(r0 + r) * 64 + k];
            #pragma unroll
            for (int kk = 0; kk < 4; kk++) {
                float4 wv = *(const float4*)&Ws[(k + kk) * 64 + c0];
                #pragma unroll
                for (int r = 0; r < 8; r++) {
                    float xs = kk == 0 ? xv[r].x : kk == 1 ? xv[r].y : kk == 2 ? xv[r].z : xv[r].w;
                    acc[r].x += xs * wv.x; acc[r].y += xs * wv.y;
                    acc[r].z += xs * wv.z; acc[r].w += xs * wv.w;
                }
            }
        }
        __syncthreads();
    }

    #pragma unroll
    for (int r = 0; r < 8; r++) {
        int gr = row0 + r0 + r;
        if (gr < n) *(float4*)&Y[(size_t)gr * 64 + c0] = acc[r];
    }
}

// ---------------- fused gather + self-loop + bias + relu (warp per node) ---------
__global__ void gather_kernel(const float* __restrict__ xw, const float* __restrict__ bias,
                              float* __restrict__ out) {
    int node = (blockIdx.x * blockDim.x + threadIdx.x) >> 5;
    if (node >= N_NODES) return;
    int lane = threadIdx.x & 31;

    int s = g_rowstart[node];
    int e = g_rowstart[node + 1];
    float dc = g_dinv[node];

    float2 acc = *(const float2*)&xw[(size_t)node * 64 + lane * 2];
    float sl = dc * dc;
    acc.x *= sl; acc.y *= sl;

    int j = s;
    for (; j + 4 <= e; j += 4) {
        Edge e0 = g_edges[j];
        Edge e1 = g_edges[j + 1];
        Edge e2 = g_edges[j + 2];
        Edge e3 = g_edges[j + 3];
        float2 v0 = *(const float2*)&xw[(size_t)e0.r * 64 + lane * 2];
        float2 v1 = *(const float2*)&xw[(size_t)e1.r * 64 + lane * 2];
        float2 v2 = *(const float2*)&xw[(size_t)e2.r * 64 + lane * 2];
        float2 v3 = *(const float2*)&xw[(size_t)e3.r * 64 + lane * 2];
        acc.x += e0.w * v0.x; acc.y += e0.w * v0.y;
        acc.x += e1.w * v1.x; acc.y += e1.w * v1.y;
        acc.x += e2.w * v2.x; acc.y += e2.w * v2.y;
        acc.x += e3.w * v3.x; acc.y += e3.w * v3.y;
    }
    for (; j < e; j++) {
        Edge e0 = g_edges[j];
        float2 v0 = *(const float2*)&xw[(size_t)e0.r * 64 + lane * 2];
        acc.x += e0.w * v0.x; acc.y += e0.w * v0.y;
    }

    float2 bv = ((const float2*)bias)[lane];
    acc.x = fmaxf(acc.x + bv.x, 0.f);
    acc.y = fmaxf(acc.y + bv.y, 0.f);
    *(float2*)&out[(size_t)node * 64 + lane * 2] = acc;
}

// ---------------- global mean pool (batch sorted -> local accumulate) ------------
#define NPB 512
__global__ void pool_kernel(const void* batch, const float* __restrict__ h) {
    int c = threadIdx.x;
    int n0 = blockIdx.x * NPB;
    if (n0 >= N_NODES) return;
    int nend = min(n0 + NPB, N_NODES);
    int is64 = g_is64;
    long long curg = ld_idx(batch, n0, is64);
    float acc = 0.f, count = 0.f;
    for (int nn = n0; nn < nend; nn++) {
        long long g = ld_idx(batch, nn, is64);
        if (g != curg) {
            atomicAdd(&g_pool[curg * HID + c], acc);
            if (c == 0) atomicAdd(&g_gcnt[curg], count);
            acc = 0.f; count = 0.f; curg = g;
        }
        acc += h[(size_t)nn * HID + c];
        count += 1.f;
    }
    atomicAdd(&g_pool[curg * HID + c], acc);
    if (c == 0) atomicAdd(&g_gcnt[curg], count);
}

// ---------------- final classifier ----------------
__global__ void final_kernel(const float* __restrict__ Wl, const float* __restrict__ bl,
                             float* __restrict__ out) {
    int g = blockIdx.x;
    int o = threadIdx.x;
    if (o >= OUT_CH) return;
    float inv = 1.0f / fmaxf(g_gcnt[g], 1.0f);
    float s = 0.0f;
    #pragma unroll
    for (int c = 0; c < HID; c++)
        s += g_pool[g * HID + c] * Wl[c * OUT_CH + o];
    out[g * OUT_CH + o] = s * inv + bl[o];
}

// ---------------- launch ----------------
extern "C" void kernel_launch(void* const* d_in, const int* in_sizes, int n_in,
                              void* d_out, int out_size) {
    const float* x  = (const float*)d_in[0];
    const float* W1 = (const float*)d_in[1];
    const float* b1 = (const float*)d_in[2];
    const float* W2 = (const float*)d_in[3];
    const float* b2 = (const float*)d_in[4];
    const float* Wl = (const float*)d_in[5];
    const float* bl = (const float*)d_in[6];
    const void*  ei = d_in[7];
    const void*  batch = d_in[8];
    float* out = (float*)d_out;

    float *xw = nullptr, *h = nullptr, *h2 = nullptr;
    cudaGetSymbolAddress((void**)&xw, g_xw);
    cudaGetSymbolAddress((void**)&h,  g_h);
    cudaGetSymbolAddress((void**)&h2, g_h2);

    const int T = 256;
    int nb_edges  = (N_EDGES + T - 1) / T;
    int nb_gemm   = (N_NODES + 127) / 128;
    int nb_gather = (N_NODES * 32 + T - 1) / T;

    zero_detect_kernel<<<SCAN_BLOCKS, T>>>(ei);       // 0
    count_kernel<<<nb_edges, T>>>(ei);                // 1
    scan_kernel<<<SCAN_BLOCKS, T>>>();                // 2
    fill_kernel<<<nb_edges, T>>>(ei);                 // 3
    gemm_kernel<IN_CH><<<nb_gemm, T>>>(x, W1, xw, N_NODES);   // 4
    gather_kernel<<<nb_gather, T>>>(xw, b1, h);       // 5  <- ncu -s 5 profiles this
    gemm_kernel<HID><<<nb_gemm, T>>>(h, W2, xw, N_NODES);     // 6
    gather_kernel<<<nb_gather, T>>>(xw, b2, h2);      // 7
    pool_kernel<<<(N_NODES + NPB - 1) / NPB, HID>>>(batch, h2); // 8
    final_kernel<<<N_GRAPHS, 32>>>(Wl, bl, out);      // 9
}